// round 4
// baseline (speedup 1.0000x reference)
#include <cuda_runtime.h>
#include <math.h>

#define B_SZ 16
#define L_SZ 160000
#define T_FR 999
#define WINS 320
#define HOPS 160
#define NCO  100
#define TM   32
#define NTHREADS 256

#define PI_D 3.14159265358979323846

typedef unsigned long long ull;

// ---------------- device-global precomputed matrices ----------------
__device__ __align__(16) float g_Dw[WINS * NCO];   // Dw[k][c] = win[k] * D[k][c]
__device__ __align__(16) float g_E [NCO * WINS];   // E[c][w]  = D[w][c]  (no window)
__device__ __align__(16) float g_WT1[NCO * NCO];   // WT[k][j] = W[j][k]
__device__ __align__(16) float g_WT2[NCO * NCO];
__device__ __align__(16) float g_WT3[NCO * NCO];

// ---------------- f32x2 helpers (Blackwell packed fp32) ----------------
__device__ __forceinline__ ull pack2(float lo, float hi) {
    ull r;
    asm("mov.b64 %0, {%1, %2};" : "=l"(r) : "f"(lo), "f"(hi));
    return r;
}
__device__ __forceinline__ void fma2(ull& d, ull a, ull b) {
    asm("fma.rn.f32x2 %0, %1, %2, %0;" : "+l"(d) : "l"(a), "l"(b));
}
__device__ __forceinline__ float2 unpack2(ull v) {
    float2 f;
    asm("mov.b64 {%0, %1}, %2;" : "=f"(f.x), "=f"(f.y) : "l"(v));
    return f;
}
__device__ __forceinline__ float clip1(float x) {
    return fminf(fmaxf(x, -1.0f), 1.0f);
}

// ---------------- init kernel: build Dw, E, transposed weights ----------------
__global__ void init_mats(const float* __restrict__ W1,
                          const float* __restrict__ W2,
                          const float* __restrict__ W3) {
    int idx = blockIdx.x * blockDim.x + threadIdx.x;
    if (idx < WINS * NCO) {
        int w = idx / NCO;
        int c = idx - w * NCO;
        double d = sqrt(2.0 / (double)WINS) * cos((w + 0.5) * PI_D / (double)WINS * (double)c);
        if (c == 0) d *= sqrt(0.5);
        double win = 0.5 * (1.0 - cos(2.0 * PI_D * (double)w / (double)WINS));
        g_Dw[w * NCO + c] = (float)(win * d);
        g_E [c * WINS + w] = (float)d;
    }
    if (idx < NCO * NCO) {
        int j = idx / NCO;
        int k = idx - j * NCO;
        g_WT1[k * NCO + j] = W1[j * NCO + k];
        g_WT2[k * NCO + j] = W2[j * NCO + k];
        g_WT3[k * NCO + j] = W3[j * NCO + k];
    }
}

// ---------------- fused pipeline kernel ----------------
// smem layout (floats): sig_n[5280] | sig_c[5280] | bufA[3200] | bufB[3200]
#define SIG_LEN  ((TM - 1) * HOPS + WINS)   // 5280
#define SMEM_FLOATS (2 * SIG_LEN + 2 * TM * NCO)
#define SMEM_BYTES  (SMEM_FLOATS * 4)

// Generic MLP stage: Bsm[r][j] = act( sum_k Asm[r][k] * WT[k][j] + bias[j] )
// ACT: 0 = prelu(alpha), 1 = tanh. WRITE_G: also write to global gout.
template <int ACT, bool WRITE_G>
__device__ __forceinline__ void mlp_stage(
    const float* __restrict__ Asm, float* __restrict__ Bsm,
    const float* __restrict__ WTg, const float* __restrict__ bias, float alpha,
    int tx, int ty, int p1i, bool hasP1,
    float* __restrict__ gout, int b, int t0)
{
    ull acc[4][2] = {};
    const ull* W64 = reinterpret_cast<const ull*>(WTg);
    #pragma unroll 4
    for (int k = 0; k < NCO; k++) {
        ull bv0 = W64[k * 50 + tx];
        ull bv1 = W64[k * 50 + p1i];
        #pragma unroll
        for (int i = 0; i < 4; i++) {
            float a = Asm[(ty + 8 * i) * NCO + k];
            ull a2 = pack2(a, a);
            fma2(acc[i][0], a2, bv0);
            fma2(acc[i][1], a2, bv1);
        }
    }
    float2 bb0 = *reinterpret_cast<const float2*>(&bias[2 * tx]);
    float2 bb1 = *reinterpret_cast<const float2*>(&bias[2 * p1i]);
    #pragma unroll
    for (int i = 0; i < 4; i++) {
        int r = ty + 8 * i;
        float2 v0 = unpack2(acc[i][0]);
        float2 v1 = unpack2(acc[i][1]);
        v0.x += bb0.x; v0.y += bb0.y;
        v1.x += bb1.x; v1.y += bb1.y;
        if (ACT == 0) {
            v0.x = (v0.x >= 0.f) ? v0.x : alpha * v0.x;
            v0.y = (v0.y >= 0.f) ? v0.y : alpha * v0.y;
            v1.x = (v1.x >= 0.f) ? v1.x : alpha * v1.x;
            v1.y = (v1.y >= 0.f) ? v1.y : alpha * v1.y;
        } else {
            v0.x = tanhf(v0.x); v0.y = tanhf(v0.y);
            v1.x = tanhf(v1.x); v1.y = tanhf(v1.y);
        }
        *reinterpret_cast<float2*>(&Bsm[r * NCO + 2 * tx]) = v0;
        if (hasP1) *reinterpret_cast<float2*>(&Bsm[r * NCO + 2 * p1i]) = v1;
        if (WRITE_G) {
            int t = t0 + r;
            if (t < T_FR) {
                float2* o = reinterpret_cast<float2*>(&gout[((size_t)b * T_FR + t) * NCO]);
                o[tx] = v0;
                if (hasP1) o[p1i] = v1;
            }
        }
    }
}

__global__ __launch_bounds__(NTHREADS, 2) void fused_kernel(
    const float* __restrict__ noisy, const float* __restrict__ clean,
    const float* __restrict__ b1, const float* __restrict__ p1g,
    const float* __restrict__ b2, const float* __restrict__ p2g,
    const float* __restrict__ b3,
    float* __restrict__ out_dct, float* __restrict__ cln_dct,
    float* __restrict__ out_sp)
{
    extern __shared__ float smem[];
    float* sig_n = smem;
    float* sig_c = smem + SIG_LEN;
    float* bufA  = smem + 2 * SIG_LEN;
    float* bufB  = bufA + TM * NCO;

    const int tid = threadIdx.x;
    const int tx  = tid & 31;          // column-pair index (pairs 0..49)
    const int ty  = tid >> 5;          // warp id 0..7 -> rows ty, ty+8, ty+16, ty+24
    const int b   = blockIdx.y;
    const int t0  = blockIdx.x * TM;
    const int nf  = min(TM, T_FR - t0);
    const int seglen = (nf - 1) * HOPS + WINS;

    const bool hasP1 = (tx < 18);              // pair 32..49
    const int  p1i   = hasP1 ? (tx + 32) : tx;

    // ---- load signal segments (float4, zero-pad tail for partial tiles) ----
    {
        const float4* nb4 = reinterpret_cast<const float4*>(noisy + (size_t)b * L_SZ + (size_t)t0 * HOPS);
        const float4* cb4 = reinterpret_cast<const float4*>(clean + (size_t)b * L_SZ + (size_t)t0 * HOPS);
        float4* sn4 = reinterpret_cast<float4*>(sig_n);
        float4* sc4 = reinterpret_cast<float4*>(sig_c);
        const int segv = seglen >> 2;
        const float4 z4 = make_float4(0.f, 0.f, 0.f, 0.f);
        for (int i = tid; i < (SIG_LEN >> 2); i += NTHREADS) {
            sn4[i] = (i < segv) ? nb4[i] : z4;
            sc4[i] = (i < segv) ? cb4[i] : z4;
        }
    }
    __syncthreads();

    // ---- Stage 1: windowed DCT for noisy & clean, K = 320 ----
    {
        ull accn[4][2] = {};
        ull accc[4][2] = {};
        const ull* Dw64 = reinterpret_cast<const ull*>(g_Dw);
        #pragma unroll 4
        for (int k = 0; k < WINS; k++) {
            ull bv0 = Dw64[k * 50 + tx];
            ull bv1 = Dw64[k * 50 + p1i];
            #pragma unroll
            for (int i = 0; i < 4; i++) {
                const int r = ty + 8 * i;
                float an = sig_n[r * HOPS + k];
                float ac = sig_c[r * HOPS + k];
                ull a2n = pack2(an, an);
                ull a2c = pack2(ac, ac);
                fma2(accn[i][0], a2n, bv0);
                fma2(accn[i][1], a2n, bv1);
                fma2(accc[i][0], a2c, bv0);
                fma2(accc[i][1], a2c, bv1);
            }
        }
        #pragma unroll
        for (int i = 0; i < 4; i++) {
            const int r = ty + 8 * i;
            const int t = t0 + r;
            float2 n0 = unpack2(accn[i][0]);
            float2 n1 = unpack2(accn[i][1]);
            float2 c0 = unpack2(accc[i][0]);
            float2 c1 = unpack2(accc[i][1]);
            n0.x = clip1(n0.x); n0.y = clip1(n0.y);
            n1.x = clip1(n1.x); n1.y = clip1(n1.y);
            c0.x = clip1(c0.x); c0.y = clip1(c0.y);
            c1.x = clip1(c1.x); c1.y = clip1(c1.y);
            *reinterpret_cast<float2*>(&bufA[r * NCO + 2 * tx]) = n0;
            if (hasP1) *reinterpret_cast<float2*>(&bufA[r * NCO + 2 * p1i]) = n1;
            if (t < T_FR) {
                float2* cd = reinterpret_cast<float2*>(&cln_dct[((size_t)b * T_FR + t) * NCO]);
                cd[tx] = c0;
                if (hasP1) cd[p1i] = c1;
            }
        }
    }
    __syncthreads();

    // ---- Stages 2-4: MLP ----
    const float alpha1 = p1g[0];
    const float alpha2 = p2g[0];

    mlp_stage<0, false>(bufA, bufB, g_WT1, b1, alpha1, tx, ty, p1i, hasP1, nullptr, b, t0);
    __syncthreads();
    mlp_stage<0, false>(bufB, bufA, g_WT2, b2, alpha2, tx, ty, p1i, hasP1, nullptr, b, t0);
    __syncthreads();
    mlp_stage<1, true >(bufA, bufB, g_WT3, b3, 0.f,    tx, ty, p1i, hasP1, out_dct, b, t0);
    __syncthreads();

    // ---- Stage 5: IDCT (K = 100, N = 320) + overlap-add via atomics ----
    {
        ull acc[4][5] = {};
        const ull* E64 = reinterpret_cast<const ull*>(g_E);
        #pragma unroll 2
        for (int k = 0; k < NCO; k++) {
            ull ev[5];
            #pragma unroll
            for (int j = 0; j < 5; j++) ev[j] = E64[k * 160 + tx + 32 * j];
            #pragma unroll
            for (int i = 0; i < 4; i++) {
                float a = bufB[(ty + 8 * i) * NCO + k];
                ull a2 = pack2(a, a);
                #pragma unroll
                for (int j = 0; j < 5; j++) fma2(acc[i][j], a2, ev[j]);
            }
        }
        #pragma unroll
        for (int i = 0; i < 4; i++) {
            const int t = t0 + ty + 8 * i;
            if (t < T_FR) {
                float* dst = out_sp + (size_t)b * L_SZ + (size_t)t * HOPS;
                #pragma unroll
                for (int j = 0; j < 5; j++) {
                    float2 v = unpack2(acc[i][j]);
                    int w = 2 * (tx + 32 * j);
                    atomicAdd(&dst[w],     v.x);
                    atomicAdd(&dst[w + 1], v.y);
                }
            }
        }
    }
}

// ---------------- launch ----------------
extern "C" void kernel_launch(void* const* d_in, const int* in_sizes, int n_in,
                              void* d_out, int out_size) {
    const float* noisy = (const float*)d_in[0];
    const float* clean = (const float*)d_in[1];
    const float* W1    = (const float*)d_in[2];
    const float* b1    = (const float*)d_in[3];
    const float* p1    = (const float*)d_in[4];
    const float* W2    = (const float*)d_in[5];
    const float* b2    = (const float*)d_in[6];
    const float* p2    = (const float*)d_in[7];
    const float* W3    = (const float*)d_in[8];
    const float* b3    = (const float*)d_in[9];

    float* out      = (float*)d_out;
    float* out_dct  = out;                                   // [16, 999, 100]
    float* cln_dct  = out + (size_t)B_SZ * T_FR * NCO;       // [16, 999, 100]
    float* out_sp   = out + 2 * (size_t)B_SZ * T_FR * NCO;   // [16, 160000]

    // zero the overlap-add target (memset node is graph-capturable)
    cudaMemsetAsync(out_sp, 0, (size_t)B_SZ * L_SZ * sizeof(float), 0);

    init_mats<<<(WINS * NCO + 255) / 256, 256>>>(W1, W2, W3);

    cudaFuncSetAttribute(fused_kernel, cudaFuncAttributeMaxDynamicSharedMemorySize, SMEM_BYTES);
    dim3 grid((T_FR + TM - 1) / TM, B_SZ);
    fused_kernel<<<grid, NTHREADS, SMEM_BYTES>>>(noisy, clean, b1, p1, b2, p2, b3,
                                                 out_dct, cln_dct, out_sp);
}

// round 5
// speedup vs baseline: 1.0128x; 1.0128x over previous
#include <cuda_runtime.h>
#include <math.h>

#define B_SZ 16
#define L_SZ 160000
#define T_FR 999
#define WINS 320
#define HOPS 160
#define NCO  100
#define TM   32
#define NTHREADS 128

#define PI_D 3.14159265358979323846

typedef unsigned long long ull;

// ---------------- device-global precomputed matrices ----------------
__device__ __align__(16) float g_Dw[WINS * NCO];   // Dw[k][c] = win[k] * D[k][c]
__device__ __align__(16) float g_E [NCO * WINS];   // E[c][w]  = D[w][c]  (no window)
__device__ __align__(16) float g_WT1[NCO * NCO];   // WT[k][j] = W[j][k]
__device__ __align__(16) float g_WT2[NCO * NCO];
__device__ __align__(16) float g_WT3[NCO * NCO];

// ---------------- f32x2 helpers ----------------
__device__ __forceinline__ ull pack2(float lo, float hi) {
    ull r;
    asm("mov.b64 %0, {%1, %2};" : "=l"(r) : "f"(lo), "f"(hi));
    return r;
}
__device__ __forceinline__ void fma2(ull& d, ull a, ull b) {
    asm("fma.rn.f32x2 %0, %1, %2, %0;" : "+l"(d) : "l"(a), "l"(b));
}
__device__ __forceinline__ float2 unpack2(ull v) {
    float2 f;
    asm("mov.b64 {%0, %1}, %2;" : "=f"(f.x), "=f"(f.y) : "l"(v));
    return f;
}
__device__ __forceinline__ float clip1(float x) {
    return fminf(fmaxf(x, -1.0f), 1.0f);
}

// ---------------- init kernel ----------------
__global__ void init_mats(const float* __restrict__ W1,
                          const float* __restrict__ W2,
                          const float* __restrict__ W3) {
    int idx = blockIdx.x * blockDim.x + threadIdx.x;
    if (idx < WINS * NCO) {
        int w = idx / NCO;
        int c = idx - w * NCO;
        double d = sqrt(2.0 / (double)WINS) * cos((w + 0.5) * PI_D / (double)WINS * (double)c);
        if (c == 0) d *= sqrt(0.5);
        double win = 0.5 * (1.0 - cos(2.0 * PI_D * (double)w / (double)WINS));
        g_Dw[w * NCO + c] = (float)(win * d);
        g_E [c * WINS + w] = (float)d;
    }
    if (idx < NCO * NCO) {
        int j = idx / NCO;
        int k = idx - j * NCO;
        g_WT1[k * NCO + j] = W1[j * NCO + k];
        g_WT2[k * NCO + j] = W2[j * NCO + k];
        g_WT3[k * NCO + j] = W3[j * NCO + k];
    }
}

// smem: sig[5280] | bufA[3200] | bufB[3200]  = 46,720 B
#define SIG_LEN  ((TM - 1) * HOPS + WINS)   // 5280
#define SMEM_FLOATS (SIG_LEN + 2 * TM * NCO)
#define SMEM_BYTES  (SMEM_FLOATS * 4)

// ---- stage-1 DCT pass over one signal. DST_SMEM: write bufA; else global only ----
template <bool DST_SMEM>
__device__ __forceinline__ void dct_pass(
    const float* __restrict__ sig, float* __restrict__ bufA,
    float* __restrict__ gdst, int b, int t0,
    int tx, int ty, int p1i, bool hasP1)
{
    ull acc[8][2] = {};
    const ull* Dw64 = reinterpret_cast<const ull*>(g_Dw);
    #pragma unroll 2
    for (int k = 0; k < WINS; k += 2) {
        ull bv0 = Dw64[k * 50 + tx];
        ull bv1 = Dw64[k * 50 + p1i];
        ull cv0 = Dw64[(k + 1) * 50 + tx];
        ull cv1 = Dw64[(k + 1) * 50 + p1i];
        #pragma unroll
        for (int i = 0; i < 8; i++) {
            float2 av = *reinterpret_cast<const float2*>(&sig[(ty + 4 * i) * HOPS + k]);
            ull ax = pack2(av.x, av.x);
            ull ay = pack2(av.y, av.y);
            fma2(acc[i][0], ax, bv0); fma2(acc[i][1], ax, bv1);
            fma2(acc[i][0], ay, cv0); fma2(acc[i][1], ay, cv1);
        }
    }
    #pragma unroll
    for (int i = 0; i < 8; i++) {
        const int r = ty + 4 * i;
        const int t = t0 + r;
        float2 v0 = unpack2(acc[i][0]);
        float2 v1 = unpack2(acc[i][1]);
        v0.x = clip1(v0.x); v0.y = clip1(v0.y);
        v1.x = clip1(v1.x); v1.y = clip1(v1.y);
        if (DST_SMEM) {
            *reinterpret_cast<float2*>(&bufA[r * NCO + 2 * tx]) = v0;
            if (hasP1) *reinterpret_cast<float2*>(&bufA[r * NCO + 2 * p1i]) = v1;
        } else if (t < T_FR) {
            float2* o = reinterpret_cast<float2*>(&gdst[((size_t)b * T_FR + t) * NCO]);
            o[tx] = v0;
            if (hasP1) o[p1i] = v1;
        }
    }
}

// ---- MLP stage. ACT: 0 = prelu, 1 = tanh. WRITE_G: also write to gout ----
template <int ACT, bool WRITE_G>
__device__ __forceinline__ void mlp_stage(
    const float* __restrict__ Asm, float* __restrict__ Bsm,
    const float* __restrict__ WTg, const float* __restrict__ bias, float alpha,
    int tx, int ty, int p1i, bool hasP1,
    float* __restrict__ gout, int b, int t0)
{
    ull acc[8][2] = {};
    const ull* W64 = reinterpret_cast<const ull*>(WTg);
    #pragma unroll 2
    for (int k = 0; k < NCO; k += 2) {
        ull bv0 = W64[k * 50 + tx];
        ull bv1 = W64[k * 50 + p1i];
        ull cv0 = W64[(k + 1) * 50 + tx];
        ull cv1 = W64[(k + 1) * 50 + p1i];
        #pragma unroll
        for (int i = 0; i < 8; i++) {
            float2 av = *reinterpret_cast<const float2*>(&Asm[(ty + 4 * i) * NCO + k]);
            ull ax = pack2(av.x, av.x);
            ull ay = pack2(av.y, av.y);
            fma2(acc[i][0], ax, bv0); fma2(acc[i][1], ax, bv1);
            fma2(acc[i][0], ay, cv0); fma2(acc[i][1], ay, cv1);
        }
    }
    float2 bb0 = *reinterpret_cast<const float2*>(&bias[2 * tx]);
    float2 bb1 = *reinterpret_cast<const float2*>(&bias[2 * p1i]);
    #pragma unroll
    for (int i = 0; i < 8; i++) {
        const int r = ty + 4 * i;
        float2 v0 = unpack2(acc[i][0]);
        float2 v1 = unpack2(acc[i][1]);
        v0.x += bb0.x; v0.y += bb0.y;
        v1.x += bb1.x; v1.y += bb1.y;
        if (ACT == 0) {
            v0.x = (v0.x >= 0.f) ? v0.x : alpha * v0.x;
            v0.y = (v0.y >= 0.f) ? v0.y : alpha * v0.y;
            v1.x = (v1.x >= 0.f) ? v1.x : alpha * v1.x;
            v1.y = (v1.y >= 0.f) ? v1.y : alpha * v1.y;
        } else {
            v0.x = tanhf(v0.x); v0.y = tanhf(v0.y);
            v1.x = tanhf(v1.x); v1.y = tanhf(v1.y);
        }
        *reinterpret_cast<float2*>(&Bsm[r * NCO + 2 * tx]) = v0;
        if (hasP1) *reinterpret_cast<float2*>(&Bsm[r * NCO + 2 * p1i]) = v1;
        if (WRITE_G) {
            const int t = t0 + r;
            if (t < T_FR) {
                float2* o = reinterpret_cast<float2*>(&gout[((size_t)b * T_FR + t) * NCO]);
                o[tx] = v0;
                if (hasP1) o[p1i] = v1;
            }
        }
    }
}

__device__ __forceinline__ void load_seg(const float* __restrict__ g, float* __restrict__ s,
                                         int seglen, int tid) {
    const float4* g4 = reinterpret_cast<const float4*>(g);
    float4* s4 = reinterpret_cast<float4*>(s);
    const int segv = seglen >> 2;
    const float4 z4 = make_float4(0.f, 0.f, 0.f, 0.f);
    for (int i = tid; i < (SIG_LEN >> 2); i += NTHREADS)
        s4[i] = (i < segv) ? g4[i] : z4;
}

__global__ __launch_bounds__(NTHREADS, 4) void fused_kernel(
    const float* __restrict__ noisy, const float* __restrict__ clean,
    const float* __restrict__ b1, const float* __restrict__ p1g,
    const float* __restrict__ b2, const float* __restrict__ p2g,
    const float* __restrict__ b3,
    float* __restrict__ out_dct, float* __restrict__ cln_dct,
    float* __restrict__ out_sp)
{
    extern __shared__ float smem[];
    float* sig  = smem;
    float* bufA = smem + SIG_LEN;
    float* bufB = bufA + TM * NCO;

    const int tid = threadIdx.x;
    const int tx  = tid & 31;          // column-pair index (pairs 0..49 with dup)
    const int ty  = tid >> 5;          // warp 0..3; warp handles rows ty+4i, i=0..7
    const int b   = blockIdx.y;
    const int t0  = blockIdx.x * TM;
    const int nf  = min(TM, T_FR - t0);
    const int seglen = (nf - 1) * HOPS + WINS;

    const bool hasP1 = (tx < 18);
    const int  p1i   = hasP1 ? (tx + 32) : tx;

    // ---- clean pass: load, DCT, store to global ----
    load_seg(clean + (size_t)b * L_SZ + (size_t)t0 * HOPS, sig, seglen, tid);
    __syncthreads();
    dct_pass<false>(sig, bufA, cln_dct, b, t0, tx, ty, p1i, hasP1);
    __syncthreads();   // everyone done reading sig before reload

    // ---- noisy pass: load, DCT, into bufA ----
    load_seg(noisy + (size_t)b * L_SZ + (size_t)t0 * HOPS, sig, seglen, tid);
    __syncthreads();
    dct_pass<true>(sig, bufA, nullptr, b, t0, tx, ty, p1i, hasP1);
    __syncthreads();

    // ---- MLP ----
    const float alpha1 = p1g[0];
    const float alpha2 = p2g[0];
    mlp_stage<0, false>(bufA, bufB, g_WT1, b1, alpha1, tx, ty, p1i, hasP1, nullptr, b, t0);
    __syncthreads();
    mlp_stage<0, false>(bufB, bufA, g_WT2, b2, alpha2, tx, ty, p1i, hasP1, nullptr, b, t0);
    __syncthreads();
    mlp_stage<1, true >(bufA, bufB, g_WT3, b3, 0.f,    tx, ty, p1i, hasP1, out_dct, b, t0);
    __syncthreads();

    // ---- IDCT + overlap-add, two 4-row passes ----
    const ull* E64 = reinterpret_cast<const ull*>(g_E);
    #pragma unroll
    for (int h = 0; h < 2; h++) {
        ull acc[4][5] = {};
        #pragma unroll 1
        for (int k = 0; k < NCO; k += 2) {
            ull ev[5], fv[5];
            #pragma unroll
            for (int j = 0; j < 5; j++) {
                ev[j] = E64[k * 160 + tx + 32 * j];
                fv[j] = E64[(k + 1) * 160 + tx + 32 * j];
            }
            #pragma unroll
            for (int i = 0; i < 4; i++) {
                const int r = ty + 4 * i + 16 * h;
                float2 av = *reinterpret_cast<const float2*>(&bufB[r * NCO + k]);
                ull ax = pack2(av.x, av.x);
                ull ay = pack2(av.y, av.y);
                #pragma unroll
                for (int j = 0; j < 5; j++) {
                    fma2(acc[i][j], ax, ev[j]);
                    fma2(acc[i][j], ay, fv[j]);
                }
            }
        }
        #pragma unroll
        for (int i = 0; i < 4; i++) {
            const int t = t0 + ty + 4 * i + 16 * h;
            if (t < T_FR) {
                float* dst = out_sp + (size_t)b * L_SZ + (size_t)t * HOPS;
                #pragma unroll
                for (int j = 0; j < 5; j++) {
                    float2 v = unpack2(acc[i][j]);
                    int w = 2 * (tx + 32 * j);
                    atomicAdd(&dst[w],     v.x);
                    atomicAdd(&dst[w + 1], v.y);
                }
            }
        }
    }
}

// ---------------- launch ----------------
extern "C" void kernel_launch(void* const* d_in, const int* in_sizes, int n_in,
                              void* d_out, int out_size) {
    const float* noisy = (const float*)d_in[0];
    const float* clean = (const float*)d_in[1];
    const float* W1    = (const float*)d_in[2];
    const float* b1    = (const float*)d_in[3];
    const float* p1    = (const float*)d_in[4];
    const float* W2    = (const float*)d_in[5];
    const float* b2    = (const float*)d_in[6];
    const float* p2    = (const float*)d_in[7];
    const float* W3    = (const float*)d_in[8];
    const float* b3    = (const float*)d_in[9];

    float* out      = (float*)d_out;
    float* out_dct  = out;                                   // [16, 999, 100]
    float* cln_dct  = out + (size_t)B_SZ * T_FR * NCO;       // [16, 999, 100]
    float* out_sp   = out + 2 * (size_t)B_SZ * T_FR * NCO;   // [16, 160000]

    cudaMemsetAsync(out_sp, 0, (size_t)B_SZ * L_SZ * sizeof(float), 0);

    init_mats<<<(WINS * NCO + 255) / 256, 256>>>(W1, W2, W3);

    cudaFuncSetAttribute(fused_kernel, cudaFuncAttributeMaxDynamicSharedMemorySize, SMEM_BYTES);
    dim3 grid((T_FR + TM - 1) / TM, B_SZ);
    fused_kernel<<<grid, NTHREADS, SMEM_BYTES>>>(noisy, clean, b1, p1, b2, p2, b3,
                                                 out_dct, cln_dct, out_sp);
}